// round 14
// baseline (speedup 1.0000x reference)
#include <cuda_runtime.h>
#include <cuda_bf16.h>
#include <cstdint>

// DotAttentionEluX — math collapses:
//   out[b,h,i,:] = (sum_j ks_j * v_j) / (sum_j ks_j)  for every row i,
//   ks_j = sum_d (elu(k[b,h,j,d]) + 1).  Query cancels entirely.
//
// R4-R13: SM-initiated writes (STG / TMA / hybrid) all pin at ~2.3TB/s
// (~7us for 16MB); every intra-device read/write overlap regressed.
// R14: route the broadcast through the COPY ENGINE instead — a tiny fill
// kernel writes 64 replicated rows per bh, then five cudaMemcpy2DAsync
// D2D graph nodes log-double the region (64->2048 rows for all 32 bh).
// The CE write path bypasses the SM->L2 ingress bottleneck.

static constexpr int B_ = 4, H_ = 8, L_ = 2048, D_ = 64;
static constexpr int BH = B_ * H_;                  // 32
static constexpr int NSPLIT = 16;
static constexpr int ROWS_PER_SPLIT = L_ / NSPLIT;  // 128
static constexpr int WARPS = 8;
static constexpr int FILL_ROWS = 64;                // seeded rows per bh

__device__ float g_num[BH * NSPLIT * D_];
__device__ float g_den[BH * NSPLIT];

__device__ __forceinline__ float elu1(float x) {
    return x > 0.0f ? x + 1.0f : __expf(x);
}

// ---------------- accum: proven R6 kernel, untouched ----------------
__global__ __launch_bounds__(256) void accum_kernel(
    const float* __restrict__ K, const float* __restrict__ V)
{
    const int blk   = blockIdx.x;       // 0..511
    const int bh    = blk / NSPLIT;
    const int split = blk % NSPLIT;
    const int warp  = threadIdx.x >> 5;
    const int lane  = threadIdx.x & 31;
    const int half  = lane >> 4;
    const int q     = lane & 15;

    const int row0 = split * ROWS_PER_SPLIT;
    const size_t base = ((size_t)bh * L_ + row0 + (size_t)warp * 2 + half) * D_
                        + (size_t)q * 4;
    const float4* __restrict__ Kp = reinterpret_cast<const float4*>(K + base);
    const float4* __restrict__ Vp = reinterpret_cast<const float4*>(V + base);
    constexpr int STRIDE4 = WARPS * 2 * D_ / 4;
    constexpr int NPAIR   = ROWS_PER_SPLIT / (WARPS * 2);   // 8

    float n0 = 0.f, n1 = 0.f, n2 = 0.f, n3 = 0.f, den = 0.f;

    #pragma unroll
    for (int r = 0; r < NPAIR; r++) {
        float4 kk = Kp[(size_t)r * STRIDE4];
        float4 vv = Vp[(size_t)r * STRIDE4];
        float ks = elu1(kk.x) + elu1(kk.y) + elu1(kk.z) + elu1(kk.w);
        #pragma unroll
        for (int o = 8; o; o >>= 1)
            ks += __shfl_xor_sync(0xffffffffu, ks, o);
        n0 += ks * vv.x;  n1 += ks * vv.y;
        n2 += ks * vv.z;  n3 += ks * vv.w;
        if (q == 0) den += ks;
    }

    __shared__ float4 s_num[WARPS * 2][D_ / 4];
    __shared__ float  s_den[WARPS * 2];
    const int wh = warp * 2 + half;
    s_num[wh][q] = make_float4(n0, n1, n2, n3);
    if (q == 0) s_den[wh] = den;
    __syncthreads();

    const int t = threadIdx.x;
    if (t < D_) {
        const float* sn = reinterpret_cast<const float*>(s_num);
        float s = 0.0f;
        #pragma unroll
        for (int w = 0; w < WARPS * 2; w++) s += sn[w * D_ + t];
        g_num[(bh * NSPLIT + split) * D_ + t] = s;
    }
    if (t == D_) {
        float s = 0.0f;
        #pragma unroll
        for (int w = 0; w < WARPS * 2; w++) s += s_den[w];
        g_den[bh * NSPLIT + split] = s;
    }
}

// ---------------- fill: seed 64 replicated rows per bh (512 KB total) ----
__global__ __launch_bounds__(256) void fill_kernel(float* __restrict__ out)
{
    const int bh = blockIdx.x;      // 0..31
    const int t  = threadIdx.x;     // 256

    __shared__ float4 s_w4[D_ / 4];

    if (t < D_) {
        const float* __restrict__ pn = g_num + bh * NSPLIT * D_ + t;
        float num = 0.0f, den = 0.0f;
        #pragma unroll
        for (int sp = 0; sp < NSPLIT; sp++) {
            num += __ldcg(pn + sp * D_);
            den += __ldcg(&g_den[bh * NSPLIT + sp]);
        }
        reinterpret_cast<float*>(s_w4)[t] = num / den;
    }
    __syncthreads();

    // 64 rows x 16 float4 = 1024 stores; 256 threads x 4, fully coalesced.
    const float4 v = s_w4[t & 15];
    float4* __restrict__ ob = reinterpret_cast<float4*>(out + (size_t)bh * L_ * D_);
    #pragma unroll
    for (int i = 0; i < 4; i++)
        ob[t + i * 256] = v;
}

extern "C" void kernel_launch(void* const* d_in, const int* in_sizes, int n_in,
                              void* d_out, int out_size)
{
    // metadata order: query, key, value. Query is mathematically irrelevant.
    const float* K = (const float*)d_in[1];
    const float* V = (const float*)d_in[2];
    float* out = (float*)d_out;

    accum_kernel<<<BH * NSPLIT, 256>>>(K, V);
    fill_kernel<<<BH, 256>>>(out);

    // Log-doubling broadcast through the copy engine: rows [0,s) -> [s,2s)
    // for all 32 bh per node (2D: pitch = bh stride, height = 32 bh).
    const size_t pitch = (size_t)L_ * D_ * sizeof(float);   // 512 KB
    char* o = (char*)d_out;
    for (int s = FILL_ROWS; s < L_; s <<= 1) {
        const size_t bytes = (size_t)s * D_ * sizeof(float);
        cudaMemcpy2DAsync(o + bytes, pitch,   // dst: rows [s, 2s)
                          o,        pitch,    // src: rows [0, s)
                          bytes, BH,
                          cudaMemcpyDeviceToDevice, 0);
    }
}

// round 16
// speedup vs baseline: 1.9080x; 1.9080x over previous
#include <cuda_runtime.h>
#include <cuda_bf16.h>
#include <cstdint>

// DotAttentionEluX — math collapses:
//   out[b,h,i,:] = (sum_j ks_j * v_j) / (sum_j ks_j)  for every row i,
//   ks_j = sum_d (elu(k[b,h,j,d]) + 1).  Query cancels entirely.
//
// R14 datum: a kernel writing only 512KB took 5.15us -> the "write floor"
// is mostly fixed latency (dependent reduce + barriers at kernel start),
// not bandwidth. R15: fold the final reduction into accum (last-arriving
// CTA per bh finalizes w[bh]); bcast becomes a bare load+4xSTG.128 kernel
// with no smem/sync/spin on its critical path.

static constexpr int B_ = 4, H_ = 8, L_ = 2048, D_ = 64;
static constexpr int BH = B_ * H_;                  // 32
static constexpr int NSPLIT = 16;
static constexpr int ROWS_PER_SPLIT = L_ / NSPLIT;  // 128
static constexpr int WARPS = 8;

__device__ float g_num[BH * NSPLIT * D_];
__device__ float g_den[BH * NSPLIT];
__device__ float g_w[BH * D_];     // final broadcast rows (8 KB)
__device__ int   g_ticket[BH];     // last-CTA election; self-resetting

__device__ __forceinline__ float elu1(float x) {
    return x > 0.0f ? x + 1.0f : __expf(x);
}

// ---------------- accum: proven R6 body + in-kernel finalization ----------
__global__ __launch_bounds__(256) void accum_kernel(
    const float* __restrict__ K, const float* __restrict__ V)
{
    const int blk   = blockIdx.x;       // 0..511
    const int bh    = blk / NSPLIT;
    const int split = blk % NSPLIT;
    const int warp  = threadIdx.x >> 5;
    const int lane  = threadIdx.x & 31;
    const int half  = lane >> 4;
    const int q     = lane & 15;

    const int row0 = split * ROWS_PER_SPLIT;
    const size_t base = ((size_t)bh * L_ + row0 + (size_t)warp * 2 + half) * D_
                        + (size_t)q * 4;
    const float4* __restrict__ Kp = reinterpret_cast<const float4*>(K + base);
    const float4* __restrict__ Vp = reinterpret_cast<const float4*>(V + base);
    constexpr int STRIDE4 = WARPS * 2 * D_ / 4;
    constexpr int NPAIR   = ROWS_PER_SPLIT / (WARPS * 2);   // 8

    float n0 = 0.f, n1 = 0.f, n2 = 0.f, n3 = 0.f, den = 0.f;

    #pragma unroll
    for (int r = 0; r < NPAIR; r++) {
        float4 kk = Kp[(size_t)r * STRIDE4];
        float4 vv = Vp[(size_t)r * STRIDE4];
        float ks = elu1(kk.x) + elu1(kk.y) + elu1(kk.z) + elu1(kk.w);
        #pragma unroll
        for (int o = 8; o; o >>= 1)
            ks += __shfl_xor_sync(0xffffffffu, ks, o);
        n0 += ks * vv.x;  n1 += ks * vv.y;
        n2 += ks * vv.z;  n3 += ks * vv.w;
        if (q == 0) den += ks;
    }

    __shared__ float4 s_num[WARPS * 2][D_ / 4];
    __shared__ float  s_den[WARPS * 2];
    __shared__ bool   s_last;
    const int wh = warp * 2 + half;
    s_num[wh][q] = make_float4(n0, n1, n2, n3);
    if (q == 0) s_den[wh] = den;
    __syncthreads();

    const int t = threadIdx.x;
    if (t < D_) {
        const float* sn = reinterpret_cast<const float*>(s_num);
        float s = 0.0f;
        #pragma unroll
        for (int w = 0; w < WARPS * 2; w++) s += sn[w * D_ + t];
        g_num[(bh * NSPLIT + split) * D_ + t] = s;
    }
    if (t == D_) {
        float s = 0.0f;
        #pragma unroll
        for (int w = 0; w < WARPS * 2; w++) s += s_den[w];
        g_den[bh * NSPLIT + split] = s;
    }

    // ----- last-CTA election per bh finalizes w[bh] inside this kernel ----
    __syncthreads();                   // all partial stores issued
    if (t == 0) {
        __threadfence();               // release partials
        s_last = (atomicAdd(&g_ticket[bh], 1) == NSPLIT - 1);
    }
    __syncthreads();

    if (s_last) {
        if (t == 0) __threadfence();   // acquire other CTAs' partials
        __syncthreads();
        if (t < D_) {
            const float* __restrict__ pn = g_num + bh * NSPLIT * D_ + t;
            float num = 0.0f, dsum = 0.0f;
            #pragma unroll
            for (int sp = 0; sp < NSPLIT; sp++) {
                num  += __ldcg(pn + sp * D_);
                dsum += __ldcg(&g_den[bh * NSPLIT + sp]);
            }
            g_w[bh * D_ + t] = num / dsum;
        }
        if (t == 0) g_ticket[bh] = 0;  // reset for next graph replay
    }
}

// ---------------- bcast: minimal critical path — ldg + 4x STG.128 ---------
static constexpr int NCHUNK = 32;                   // 64-row chunks per bh
static constexpr int CROWS  = L_ / NCHUNK;          // 64

__global__ __launch_bounds__(256) void bcast_kernel(float* __restrict__ out)
{
    const int chunk = blockIdx.x;     // 0..31
    const int bh    = blockIdx.y;     // 0..31
    const int t     = threadIdx.x;    // 256

    // One 256B row per bh, broadcast across the block (1-2 L2 lines).
    const float4 v = __ldg(reinterpret_cast<const float4*>(g_w + bh * D_)
                           + (t & 15));

    float4* __restrict__ ob = reinterpret_cast<float4*>(
        out + ((size_t)bh * L_ + (size_t)chunk * CROWS) * D_);
    // 64 rows * 16 float4 = 1024; 256 threads x 4, fully coalesced.
    #pragma unroll
    for (int i = 0; i < 4; i++)
        ob[t + i * 256] = v;
}

extern "C" void kernel_launch(void* const* d_in, const int* in_sizes, int n_in,
                              void* d_out, int out_size)
{
    // metadata order: query, key, value. Query is mathematically irrelevant.
    const float* K = (const float*)d_in[1];
    const float* V = (const float*)d_in[2];
    float* out = (float*)d_out;

    accum_kernel<<<BH * NSPLIT, 256>>>(K, V);
    bcast_kernel<<<dim3(NCHUNK, BH), 256>>>(out);
}

// round 17
// speedup vs baseline: 2.3897x; 1.2525x over previous
#include <cuda_runtime.h>
#include <cuda_bf16.h>
#include <cstdint>

// DotAttentionEluX — math collapses:
//   out[b,h,i,:] = (sum_j ks_j * v_j) / (sum_j ks_j)  for every row i,
//   ks_j = sum_d (elu(k[b,h,j,d]) + 1).  Query cancels entirely.
//
// R16: minimal bcast hit 6.0us (store-path ceiling ~2.7TB/s) but accum
// regressed ~5.5->10us — suspected cause: per-CTA __threadfence() (gpu
// scope => CCTL.IVALL L1-flush) x512. R17: release semantics carried on
// the arrive atomic itself (atom.release.gpu.add) — no fence instruction
// in the common path; only the 32 winner CTAs issue fence.acquire.

static constexpr int B_ = 4, H_ = 8, L_ = 2048, D_ = 64;
static constexpr int BH = B_ * H_;                  // 32
static constexpr int NSPLIT = 16;
static constexpr int ROWS_PER_SPLIT = L_ / NSPLIT;  // 128
static constexpr int WARPS = 8;

__device__ float g_num[BH * NSPLIT * D_];
__device__ float g_den[BH * NSPLIT];
__device__ float g_w[BH * D_];     // final broadcast rows (8 KB)
__device__ int   g_ticket[BH];     // last-CTA election; self-resetting

__device__ __forceinline__ float elu1(float x) {
    return x > 0.0f ? x + 1.0f : __expf(x);
}

// ---------------- accum: proven R6 body + fence-free finalization ---------
__global__ __launch_bounds__(256) void accum_kernel(
    const float* __restrict__ K, const float* __restrict__ V)
{
    const int blk   = blockIdx.x;       // 0..511
    const int bh    = blk / NSPLIT;
    const int split = blk % NSPLIT;
    const int warp  = threadIdx.x >> 5;
    const int lane  = threadIdx.x & 31;
    const int half  = lane >> 4;
    const int q     = lane & 15;

    const int row0 = split * ROWS_PER_SPLIT;
    const size_t base = ((size_t)bh * L_ + row0 + (size_t)warp * 2 + half) * D_
                        + (size_t)q * 4;
    const float4* __restrict__ Kp = reinterpret_cast<const float4*>(K + base);
    const float4* __restrict__ Vp = reinterpret_cast<const float4*>(V + base);
    constexpr int STRIDE4 = WARPS * 2 * D_ / 4;
    constexpr int NPAIR   = ROWS_PER_SPLIT / (WARPS * 2);   // 8

    float n0 = 0.f, n1 = 0.f, n2 = 0.f, n3 = 0.f, den = 0.f;

    #pragma unroll
    for (int r = 0; r < NPAIR; r++) {
        float4 kk = Kp[(size_t)r * STRIDE4];
        float4 vv = Vp[(size_t)r * STRIDE4];
        float ks = elu1(kk.x) + elu1(kk.y) + elu1(kk.z) + elu1(kk.w);
        #pragma unroll
        for (int o = 8; o; o >>= 1)
            ks += __shfl_xor_sync(0xffffffffu, ks, o);
        n0 += ks * vv.x;  n1 += ks * vv.y;
        n2 += ks * vv.z;  n3 += ks * vv.w;
        if (q == 0) den += ks;
    }

    __shared__ float4 s_num[WARPS * 2][D_ / 4];
    __shared__ float  s_den[WARPS * 2];
    __shared__ int    s_last;
    const int wh = warp * 2 + half;
    s_num[wh][q] = make_float4(n0, n1, n2, n3);
    if (q == 0) s_den[wh] = den;
    __syncthreads();

    const int t = threadIdx.x;
    if (t < D_) {
        const float* sn = reinterpret_cast<const float*>(s_num);
        float s = 0.0f;
        #pragma unroll
        for (int w = 0; w < WARPS * 2; w++) s += sn[w * D_ + t];
        // Write partials with .cg (L2): avoids L1 involvement and makes the
        // release-atomic ordering cheap.
        __stcg(&g_num[(bh * NSPLIT + split) * D_ + t], s);
    }
    if (t == D_) {
        float s = 0.0f;
        #pragma unroll
        for (int w = 0; w < WARPS * 2; w++) s += s_den[w];
        __stcg(&g_den[bh * NSPLIT + split], s);
    }

    // ----- last-CTA election: release rides on the atomic (no membar) -----
    __syncthreads();                   // all partial stores issued
    if (t == 0) {
        int old;
        asm volatile("atom.release.gpu.global.add.s32 %0, [%1], 1;"
                     : "=r"(old) : "l"(&g_ticket[bh]) : "memory");
        s_last = (old == NSPLIT - 1);
    }
    __syncthreads();

    if (s_last) {
        if (t == 0)
            asm volatile("fence.acquire.gpu;" ::: "memory");
        __syncthreads();               // acquire visible to whole CTA
        if (t < D_) {
            const float* __restrict__ pn = g_num + bh * NSPLIT * D_ + t;
            float num = 0.0f, dsum = 0.0f;
            #pragma unroll
            for (int sp = 0; sp < NSPLIT; sp++) {
                num  += __ldcg(pn + sp * D_);
                dsum += __ldcg(&g_den[bh * NSPLIT + sp]);
            }
            __stcg(&g_w[bh * D_ + t], num / dsum);
        }
        if (t == 0) g_ticket[bh] = 0;  // reset for next graph replay
    }
}

// ---------------- bcast: minimal critical path — ldg + 4x STG.128 ---------
static constexpr int NCHUNK = 32;                   // 64-row chunks per bh
static constexpr int CROWS  = L_ / NCHUNK;          // 64

__global__ __launch_bounds__(256) void bcast_kernel(float* __restrict__ out)
{
    const int chunk = blockIdx.x;     // 0..31
    const int bh    = blockIdx.y;     // 0..31
    const int t     = threadIdx.x;    // 256

    // One 256B row per bh, broadcast across the block (1-2 L2 lines).
    const float4 v = __ldg(reinterpret_cast<const float4*>(g_w + bh * D_)
                           + (t & 15));

    float4* __restrict__ ob = reinterpret_cast<float4*>(
        out + ((size_t)bh * L_ + (size_t)chunk * CROWS) * D_);
    // 64 rows * 16 float4 = 1024; 256 threads x 4, fully coalesced.
    #pragma unroll
    for (int i = 0; i < 4; i++)
        ob[t + i * 256] = v;
}

extern "C" void kernel_launch(void* const* d_in, const int* in_sizes, int n_in,
                              void* d_out, int out_size)
{
    // metadata order: query, key, value. Query is mathematically irrelevant.
    const float* K = (const float*)d_in[1];
    const float* V = (const float*)d_in[2];
    float* out = (float*)d_out;

    accum_kernel<<<BH * NSPLIT, 256>>>(K, V);
    bcast_kernel<<<dim3(NCHUNK, BH), 256>>>(out);
}